// round 16
// baseline (speedup 1.0000x reference)
#include <cuda_runtime.h>
#include <cuda_fp16.h>
#include <math.h>
#include <stdint.h>

#define TOK   8192
#define DM    1024
#define DFF   4096
#define NH    16
#define DK    64
#define SEQ   2048
#define BATCH 4
#define QLD   (3 * DM)

// ---------------- scratch ----------------
__device__ __half g_h   [TOK * DM];
__device__ __half g_qkv [TOK * QLD];
__device__ __half g_ctx [TOK * DM];
__device__ float  g_x1  [TOK * DM];
__device__ __half g_h2  [TOK * DM];
__device__ __half g_ff  [TOK * DFF];
// fp16 weights, transposed to [N][K]
__device__ __half g_wqkvT[QLD * DM];
__device__ float  g_bqkv [QLD];
__device__ __half g_woT  [DM * DM];
__device__ __half g_w1T  [DFF * DM];
__device__ __half g_w2T  [DM * DFF];

// ---------------- helpers ----------------
__device__ __forceinline__ uint32_t smem_u32(const void* p) {
    uint32_t a;
    asm("{ .reg .u64 t; cvta.to.shared.u64 t, %1; cvt.u32.u64 %0, t; }" : "=r"(a) : "l"(p));
    return a;
}
__device__ __forceinline__ void cp_async16(uint32_t dst, const void* src) {
    asm volatile("cp.async.cg.shared.global [%0], [%1], 16;" :: "r"(dst), "l"(src));
}
__device__ __forceinline__ void cp_commit() {
    asm volatile("cp.async.commit_group;" ::: "memory");
}
__device__ __forceinline__ void prefetch_l2(const void* p) {
    asm volatile("prefetch.global.L2 [%0];" :: "l"(p));
}
__device__ __forceinline__ void mma_f16_16x8x16(float* d, const uint32_t* a, const uint32_t* b) {
    asm volatile(
        "mma.sync.aligned.m16n8k16.row.col.f32.f16.f16.f32 "
        "{%0,%1,%2,%3}, {%4,%5,%6,%7}, {%8,%9}, {%0,%1,%2,%3};"
        : "+f"(d[0]), "+f"(d[1]), "+f"(d[2]), "+f"(d[3])
        : "r"(a[0]), "r"(a[1]), "r"(a[2]), "r"(a[3]), "r"(b[0]), "r"(b[1]));
}
__device__ __forceinline__ void ldmatrix_x4(uint32_t* r, uint32_t addr) {
    asm volatile("ldmatrix.sync.aligned.m8n8.x4.shared.b16 {%0,%1,%2,%3}, [%4];"
        : "=r"(r[0]), "=r"(r[1]), "=r"(r[2]), "=r"(r[3]) : "r"(addr));
}
__device__ __forceinline__ void ldmatrix_x4_trans(uint32_t* r, uint32_t addr) {
    asm volatile("ldmatrix.sync.aligned.m8n8.x4.trans.shared.b16 {%0,%1,%2,%3}, [%4];"
        : "=r"(r[0]), "=r"(r[1]), "=r"(r[2]), "=r"(r[3]) : "r"(addr));
}
__device__ __forceinline__ uint32_t pack_h2(float x, float y) {
    __half2 h = __floats2half2_rn(x, y);
    return *(uint32_t*)&h;
}

// ---------------- fused prep + LN1: ONE launch ----------------
#define PREP_BLOCKS 6145
#define PREPLN_BLOCKS (PREP_BLOCKS + TOK)

__global__ void __launch_bounds__(256) prep_ln_kernel(
    const float* __restrict__ Wq, const float* __restrict__ Wk, const float* __restrict__ Wv,
    const float* __restrict__ bq, const float* __restrict__ bk, const float* __restrict__ bv,
    const float* __restrict__ Wo, const float* __restrict__ W1, const float* __restrict__ W2,
    __half* __restrict__ wqkvT, float* __restrict__ bqkv,
    __half* __restrict__ woT, __half* __restrict__ w1T, __half* __restrict__ w2T,
    const float* __restrict__ x, const float* __restrict__ ln1g, const float* __restrict__ ln1b,
    __half* __restrict__ hout)
{
    const int id = blockIdx.x;
    const int t = threadIdx.x;

    if (id >= PREP_BLOCKS) {
        // ---- LN1 row ----
        const int row = id - PREP_BLOCKS;
        const float4 v = ((const float4*)(x + (size_t)row * DM))[t];

        float s  = v.x + v.y + v.z + v.w;
        float ss = v.x * v.x + v.y * v.y + v.z * v.z + v.w * v.w;
        #pragma unroll
        for (int o = 16; o; o >>= 1) {
            s  += __shfl_xor_sync(0xffffffffu, s,  o);
            ss += __shfl_xor_sync(0xffffffffu, ss, o);
        }
        __shared__ float sb[8], sb2[8];
        if ((t & 31) == 0) { sb[t >> 5] = s; sb2[t >> 5] = ss; }
        __syncthreads();
        float ts = 0.f, ts2 = 0.f;
        #pragma unroll
        for (int i = 0; i < 8; i++) { ts += sb[i]; ts2 += sb2[i]; }

        const float mu  = ts * (1.0f / DM);
        const float var = ts2 * (1.0f / DM) - mu * mu;
        const float inv = rsqrtf(var + 1e-5f);

        const float4 gg = ((const float4*)ln1g)[t];
        const float4 bb = ((const float4*)ln1b)[t];
        uint2 o;
        o.x = pack_h2((v.x - mu) * inv * gg.x + bb.x, (v.y - mu) * inv * gg.y + bb.y);
        o.y = pack_h2((v.z - mu) * inv * gg.z + bb.z, (v.w - mu) * inv * gg.w + bb.w);
        ((uint2*)(hout + (size_t)row * DM))[t] = o;
        return;
    }

    if (id == PREP_BLOCKS - 1) {
        #pragma unroll
        for (int j = 0; j < 3; j++) {
            const int idx = j * 256 + t;
            const int which = idx >> 8, c4 = idx & 255;
            const float* src = which == 0 ? bq : (which == 1 ? bk : bv);
            ((float4*)bqkv)[which * 256 + c4] = ((const float4*)src)[c4];
        }
        return;
    }

    const int tx = t & 31, ty = t >> 5;
    const float* in; __half* out; int R, C, lid;
    if (id < 2048) {
        const int m = id >> 9; lid = id & 511;
        in = m == 0 ? Wq : (m == 1 ? Wk : (m == 2 ? Wv : Wo));
        out = (m == 3) ? woT : (wqkvT + (size_t)m * DM * DM);
        R = DM; C = DM;
    } else if (id < 4096) {
        lid = id - 2048; in = W1; out = w1T; R = DM; C = DFF;
    } else {
        lid = id - 4096; in = W2; out = w2T; R = DFF; C = DM;
    }
    const int tilesC = C / 32;
    const int r0 = (lid / tilesC) * 64, c0 = (lid % tilesC) * 32;

    __shared__ float tile[64][33];
    #pragma unroll
    for (int i = ty; i < 64; i += 8)
        tile[i][tx] = in[(size_t)(r0 + i) * C + c0 + tx];
    __syncthreads();

    const int orow = t >> 3, seg = t & 7;
    float f[8];
    #pragma unroll
    for (int j = 0; j < 8; j++) f[j] = tile[seg * 8 + j][orow];
    uint4 u;
    u.x = pack_h2(f[0], f[1]); u.y = pack_h2(f[2], f[3]);
    u.z = pack_h2(f[4], f[5]); u.w = pack_h2(f[6], f[7]);
    *(uint4*)(out + (size_t)(c0 + orow) * R + r0 + seg * 8) = u;
}

// ---------------- LayerNorm (standalone, for LN2) ----------------
__global__ void __launch_bounds__(256) ln_kernel(const float* __restrict__ x,
                                                 const float* __restrict__ g,
                                                 const float* __restrict__ b,
                                                 __half* __restrict__ out)
{
    const int row = blockIdx.x;
    const int tid = threadIdx.x;
    const float4 v = ((const float4*)(x + (size_t)row * DM))[tid];

    float s  = v.x + v.y + v.z + v.w;
    float ss = v.x * v.x + v.y * v.y + v.z * v.z + v.w * v.w;
    #pragma unroll
    for (int o = 16; o; o >>= 1) {
        s  += __shfl_xor_sync(0xffffffffu, s,  o);
        ss += __shfl_xor_sync(0xffffffffu, ss, o);
    }
    __shared__ float sb[8], sb2[8];
    if ((tid & 31) == 0) { sb[tid >> 5] = s; sb2[tid >> 5] = ss; }
    __syncthreads();
    float ts = 0.f, ts2 = 0.f;
    #pragma unroll
    for (int i = 0; i < 8; i++) { ts += sb[i]; ts2 += sb2[i]; }

    const float mu  = ts * (1.0f / DM);
    const float var = ts2 * (1.0f / DM) - mu * mu;
    const float inv = rsqrtf(var + 1e-5f);

    const float4 gg = ((const float4*)g)[tid];
    const float4 bb = ((const float4*)b)[tid];
    uint2 o;
    o.x = pack_h2((v.x - mu) * inv * gg.x + bb.x, (v.y - mu) * inv * gg.y + bb.y);
    o.y = pack_h2((v.z - mu) * inv * gg.z + bb.z, (v.w - mu) * inv * gg.w + bb.w);
    ((uint2*)(out + (size_t)row * DM))[tid] = o;
}

// ---------------- GELU ----------------
__device__ __forceinline__ float gelu_exact(float v) {
    return 0.5f * v * (1.0f + erff(v * 0.70710678118654752440f));
}

// ---------------- fp16 GEMM: 128x64 tile, warp 32x32, 2-stage, 3 CTAs/SM ----------------
#define BM 128
#define BN 64
#define BKH 64
#define TSH 72                          // halves per smem row = 144 bytes
#define A_TILE_HALVES (BM * TSH)
#define B_TILE_HALVES (BN * TSH)
#define STAGE_BYTES ((A_TILE_HALVES + B_TILE_HALVES) * 2)
#define GEMM_SMEM_BYTES (2 * STAGE_BYTES)

template <int EPI, int OUTH>
__global__ void __launch_bounds__(256, 3) gemm_f16(
    const __half* __restrict__ A, const __half* __restrict__ BT,
    const float* __restrict__ bias, const float* __restrict__ res,
    void* __restrict__ Cv, int M, int N, int K)
{
    extern __shared__ __half smh[];
    const uint32_t sbase = smem_u32(smh);

    const int tid = threadIdx.x;
    const int wid = tid >> 5;
    const int lane = tid & 31;
    const int g = lane >> 2;
    const int tig = lane & 3;
    const int wm = wid & 3;
    const int wn = wid >> 2;

    const uint32_t aRow  = (uint32_t)((lane & 15) * 144 + (lane >> 4) * 16);
    const uint32_t bRow2 = (uint32_t)((lane & 7) * 144 + ((lane >> 3) & 1) * 16 + (lane >> 4) * (8 * 144));

    const int n0 = blockIdx.x * BN;
    const int m0 = blockIdx.y * BM;
    const int NT = K / BKH;

    float acc[2][4][4];
    #pragma unroll
    for (int mt = 0; mt < 2; mt++)
        #pragma unroll
        for (int nt = 0; nt < 4; nt++)
            #pragma unroll
            for (int e = 0; e < 4; e++) acc[mt][nt][e] = 0.f;

    auto load_stage = [&](int st, int t) {
        const uint32_t aoff = sbase + (uint32_t)st * STAGE_BYTES;
        const uint32_t boff = aoff + A_TILE_HALVES * 2;
        #pragma unroll
        for (int i = 0; i < 6; i++) {
            const int idx = i * 256 + tid;
            if (idx < 1024) {
                const int row = idx >> 3, ch = idx & 7;
                cp_async16(aoff + (uint32_t)(row * TSH + ch * 8) * 2u,
                           A + (size_t)(m0 + row) * K + (size_t)t * BKH + ch * 8);
            } else {
                const int j = idx - 1024;
                const int row = j >> 3, ch = j & 7;
                cp_async16(boff + (uint32_t)(row * TSH + ch * 8) * 2u,
                           BT + (size_t)(n0 + row) * K + (size_t)t * BKH + ch * 8);
            }
        }
    };

    load_stage(0, 0);
    cp_commit();

    // warm L2 with the residual tile we'll read in the epilogue (128 rows x 64 fp32
    // = 256 x 128B lines; one line per thread). No registers consumed.
    if (EPI == 1) {
        const int prow = tid >> 1, phalf = tid & 1;
        prefetch_l2(res + (size_t)(m0 + prow) * N + n0 + phalf * 32);
    }

    for (int t = 0; t < NT; t++) {
        asm volatile("cp.async.wait_group 0;" ::: "memory");
        __syncthreads();

        if (t + 1 < NT) { load_stage((t + 1) & 1, t + 1); cp_commit(); }

        const int st = t & 1;
        const uint32_t aBase = sbase + (uint32_t)st * STAGE_BYTES + (uint32_t)(wm * 32) * 144 + aRow;
        const uint32_t bBase = sbase + (uint32_t)st * STAGE_BYTES + A_TILE_HALVES * 2
                             + (uint32_t)(wn * 32) * 144 + bRow2;

        #pragma unroll
        for (int ks = 0; ks < 4; ks++) {
            const uint32_t kb = (uint32_t)(ks * 32);
            uint32_t afr[2][4], bfr[2][4];
            #pragma unroll
            for (int mt = 0; mt < 2; mt++)
                ldmatrix_x4(afr[mt], aBase + (uint32_t)(mt * 16) * 144 + kb);
            #pragma unroll
            for (int p = 0; p < 2; p++)
                ldmatrix_x4(bfr[p], bBase + (uint32_t)(p * 16) * 144 + kb);
            #pragma unroll
            for (int mt = 0; mt < 2; mt++)
                #pragma unroll
                for (int nt = 0; nt < 4; nt++)
                    mma_f16_16x8x16(acc[mt][nt], afr[mt], &bfr[nt >> 1][(nt & 1) * 2]);
        }
    }

    #pragma unroll
    for (int mt = 0; mt < 2; mt++) {
        const int r0 = m0 + wm * 32 + mt * 16 + g;
        const float* rr0 = (EPI == 1) ? (res + (size_t)r0 * N) : nullptr;
        const float* rr1 = (EPI == 1) ? (res + (size_t)(r0 + 8) * N) : nullptr;
        #pragma unroll
        for (int nt = 0; nt < 4; nt++) {
            const int col = n0 + wn * 32 + nt * 8 + 2 * tig;
            const float bx = bias[col], by = bias[col + 1];
            float v0 = acc[mt][nt][0] + bx, v1 = acc[mt][nt][1] + by;
            float v2 = acc[mt][nt][2] + bx, v3 = acc[mt][nt][3] + by;
            if (EPI == 2) {
                v0 = gelu_exact(v0); v1 = gelu_exact(v1);
                v2 = gelu_exact(v2); v3 = gelu_exact(v3);
            }
            if (EPI == 1) {
                v0 += rr0[col]; v1 += rr0[col + 1];
                v2 += rr1[col]; v3 += rr1[col + 1];
            }
            if (OUTH) {
                __half* C = (__half*)Cv;
                *(uint32_t*)(C + (size_t)r0 * N + col)       = pack_h2(v0, v1);
                *(uint32_t*)(C + (size_t)(r0 + 8) * N + col) = pack_h2(v2, v3);
            } else {
                float* C = (float*)Cv;
                *(float2*)(C + (size_t)r0 * N + col)       = make_float2(v0, v1);
                *(float2*)(C + (size_t)(r0 + 8) * N + col) = make_float2(v2, v3);
            }
        }
    }
}

// ---------------- fp16 flash attention: register-resident P ----------------
#define KV 64
#define KSH 72
#define VSH 72
#define K_TILE_HALVES (KV * KSH)
#define V_TILE_HALVES (KV * VSH)
#define ATTN_SMEM ((2 * K_TILE_HALVES + 2 * V_TILE_HALVES) * 2)

__global__ void __launch_bounds__(256, 2) attn_f16_kernel(const __half* __restrict__ qkv,
                                                          __half* __restrict__ out)
{
    extern __shared__ __half smh[];
    const uint32_t sbase = smem_u32(smh);
    const uint32_t vtsBase = sbase + 2 * K_TILE_HALVES * 2;

    const int tid = threadIdx.x;
    const int w = tid >> 5;
    const int lane = tid & 31;
    const int g = lane >> 2;
    const int tig = lane & 3;

    const uint32_t bRow2 = (uint32_t)((lane & 7) * 144 + ((lane >> 3) & 1) * 16 + (lane >> 4) * (8 * 144));
    const uint32_t vRowT = (uint32_t)(((lane & 7) + ((lane >> 3) & 1) * 8) * 144 + (lane >> 4) * 16);

    const int qt = blockIdx.x, h = blockIdx.y, b = blockIdx.z;

    uint32_t qa[4][4];
    {
        const __half* qb = qkv + ((size_t)(b * SEQ + qt * 128 + w * 16)) * QLD + h * DK;
        const __half2 sc = __floats2half2_rn(0.125f, 0.125f);
        #pragma unroll
        for (int ks = 0; ks < 4; ks++) {
            const int c = ks * 16 + 2 * tig;
            __half2 a0 = __hmul2(*(const __half2*)(qb + (size_t)g * QLD + c), sc);
            __half2 a1 = __hmul2(*(const __half2*)(qb + (size_t)(g + 8) * QLD + c), sc);
            __half2 a2 = __hmul2(*(const __half2*)(qb + (size_t)g * QLD + c + 8), sc);
            __half2 a3 = __hmul2(*(const __half2*)(qb + (size_t)(g + 8) * QLD + c + 8), sc);
            qa[ks][0] = *(uint32_t*)&a0; qa[ks][1] = *(uint32_t*)&a1;
            qa[ks][2] = *(uint32_t*)&a2; qa[ks][3] = *(uint32_t*)&a3;
        }
    }

    float o[8][4];
    #pragma unroll
    for (int nt = 0; nt < 8; nt++)
        #pragma unroll
        for (int e = 0; e < 4; e++) o[nt][e] = 0.f;
    float m0 = -1e30f, m1 = -1e30f, l0 = 0.f, l1 = 0.f;

    auto load_kv = [&](int t, int buf) {
        const uint32_t kdst = sbase + (uint32_t)(buf * K_TILE_HALVES) * 2u;
        const uint32_t vdst = vtsBase + (uint32_t)(buf * V_TILE_HALVES) * 2u;
        const __half* ksrc = qkv + ((size_t)(b * SEQ + t * KV)) * QLD + DM + h * DK;
        const __half* vsrc = qkv + ((size_t)(b * SEQ + t * KV)) * QLD + 2 * DM + h * DK;
        const int kr0 = tid >> 3, kc = tid & 7;
        cp_async16(kdst + (uint32_t)(kr0 * KSH + kc * 8) * 2u,
                   ksrc + (size_t)kr0 * QLD + kc * 8);
        cp_async16(kdst + (uint32_t)((kr0 + 32) * KSH + kc * 8) * 2u,
                   ksrc + (size_t)(kr0 + 32) * QLD + kc * 8);
        cp_async16(vdst + (uint32_t)(kr0 * VSH + kc * 8) * 2u,
                   vsrc + (size_t)kr0 * QLD + kc * 8);
        cp_async16(vdst + (uint32_t)((kr0 + 32) * VSH + kc * 8) * 2u,
                   vsrc + (size_t)(kr0 + 32) * QLD + kc * 8);
    };

    load_kv(0, 0);
    cp_commit();

    const int NKV = SEQ / KV;
    for (int t = 0; t < NKV; t++) {
        asm volatile("cp.async.wait_group 0;" ::: "memory");
        __syncthreads();
        if (t + 1 < NKV) { load_kv(t + 1, (t + 1) & 1); cp_commit(); }

        float s[8][4];
        #pragma unroll
        for (int nt = 0; nt < 8; nt++)
            #pragma unroll
            for (int e = 0; e < 4; e++) s[nt][e] = 0.f;
        {
            const uint32_t kTile = sbase + (uint32_t)((t & 1) * K_TILE_HALVES) * 2u + bRow2;
            #pragma unroll
            for (int ks = 0; ks < 4; ks++) {
                const uint32_t kb = (uint32_t)(ks * 32);
                #pragma unroll
                for (int p = 0; p < 4; p++) {
                    uint32_t bp[4];
                    ldmatrix_x4(bp, kTile + (uint32_t)(p * 16) * 144 + kb);
                    mma_f16_16x8x16(s[2 * p],     qa[ks], bp);
                    mma_f16_16x8x16(s[2 * p + 1], qa[ks], bp + 2);
                }
            }
        }

        float rmax0 = -1e30f, rmax1 = -1e30f;
        #pragma unroll
        for (int nt = 0; nt < 8; nt++) {
            rmax0 = fmaxf(rmax0, fmaxf(s[nt][0], s[nt][1]));
            rmax1 = fmaxf(rmax1, fmaxf(s[nt][2], s[nt][3]));
        }
        rmax0 = fmaxf(rmax0, __shfl_xor_sync(0xffffffffu, rmax0, 1));
        rmax0 = fmaxf(rmax0, __shfl_xor_sync(0xffffffffu, rmax0, 2));
        rmax1 = fmaxf(rmax1, __shfl_xor_sync(0xffffffffu, rmax1, 1));
        rmax1 = fmaxf(rmax1, __shfl_xor_sync(0xffffffffu, rmax1, 2));

        const float mn0 = fmaxf(m0, rmax0);
        const float mn1 = fmaxf(m1, rmax1);
        const float al0 = __expf(m0 - mn0);
        const float al1 = __expf(m1 - mn1);
        m0 = mn0; m1 = mn1;

        uint32_t pa[4][4];
        float rs0 = 0.f, rs1 = 0.f;
        #pragma unroll
        for (int ks = 0; ks < 4; ks++) {
            const float p00 = __expf(s[2 * ks][0] - mn0);
            const float p01 = __expf(s[2 * ks][1] - mn0);
            const float p02 = __expf(s[2 * ks][2] - mn1);
            const float p03 = __expf(s[2 * ks][3] - mn1);
            const float p10 = __expf(s[2 * ks + 1][0] - mn0);
            const float p11 = __expf(s[2 * ks + 1][1] - mn0);
            const float p12 = __expf(s[2 * ks + 1][2] - mn1);
            const float p13 = __expf(s[2 * ks + 1][3] - mn1);
            rs0 += (p00 + p01) + (p10 + p11);
            rs1 += (p02 + p03) + (p12 + p13);
            pa[ks][0] = pack_h2(p00, p01);
            pa[ks][1] = pack_h2(p02, p03);
            pa[ks][2] = pack_h2(p10, p11);
            pa[ks][3] = pack_h2(p12, p13);
        }
        rs0 += __shfl_xor_sync(0xffffffffu, rs0, 1);
        rs0 += __shfl_xor_sync(0xffffffffu, rs0, 2);
        rs1 += __shfl_xor_sync(0xffffffffu, rs1, 1);
        rs1 += __shfl_xor_sync(0xffffffffu, rs1, 2);
        l0 = l0 * al0 + rs0;
        l1 = l1 * al1 + rs1;

        #pragma unroll
        for (int nt = 0; nt < 8; nt++) {
            o[nt][0] *= al0; o[nt][1] *= al0;
            o[nt][2] *= al1; o[nt][3] *= al1;
        }

        {
            const uint32_t vTile = vtsBase + (uint32_t)((t & 1) * V_TILE_HALVES) * 2u + vRowT;
            #pragma unroll
            for (int ks = 0; ks < 4; ks++) {
                const uint32_t vk = vTile + (uint32_t)(ks * 16) * 144;
                #pragma unroll
                for (int p = 0; p < 4; p++) {
                    uint32_t bp[4];
                    ldmatrix_x4_trans(bp, vk + (uint32_t)(p * 32));
                    mma_f16_16x8x16(o[2 * p],     pa[ks], bp);
                    mma_f16_16x8x16(o[2 * p + 1], pa[ks], bp + 2);
                }
            }
        }
    }

    {
        const float i0 = 1.0f / l0, i1 = 1.0f / l1;
        const int r0 = qt * 128 + w * 16 + g;
        __half* ob0 = out + ((size_t)(b * SEQ + r0)) * DM + h * DK + 2 * tig;
        __half* ob1 = ob0 + 8 * DM;
        #pragma unroll
        for (int nt = 0; nt < 8; nt++) {
            *(uint32_t*)(ob0 + nt * 8) = pack_h2(o[nt][0] * i0, o[nt][1] * i0);
            *(uint32_t*)(ob1 + nt * 8) = pack_h2(o[nt][2] * i1, o[nt][3] * i1);
        }
    }
}

// ---------------- host launcher ----------------
extern "C" void kernel_launch(void* const* d_in, const int* in_sizes, int n_in,
                              void* d_out, int out_size)
{
    (void)in_sizes; (void)n_in; (void)out_size;
    const float* x     = (const float*)d_in[0];
    const float* Wq    = (const float*)d_in[1];
    const float* bq    = (const float*)d_in[2];
    const float* Wk    = (const float*)d_in[3];
    const float* bk    = (const float*)d_in[4];
    const float* Wv    = (const float*)d_in[5];
    const float* bv    = (const float*)d_in[6];
    const float* Wo    = (const float*)d_in[7];
    const float* bo    = (const float*)d_in[8];
    const float* ln1_g = (const float*)d_in[9];
    const float* ln1_b = (const float*)d_in[10];
    const float* W1    = (const float*)d_in[11];
    const float* b1    = (const float*)d_in[12];
    const float* W2    = (const float*)d_in[13];
    const float* b2    = (const float*)d_in[14];
    const float* ln2_g = (const float*)d_in[15];
    const float* ln2_b = (const float*)d_in[16];
    float* out = (float*)d_out;

    __half *h, *qkv, *ctx, *h2, *ff, *wqkvT, *woT, *w1T, *w2T;
    float *x1, *bqkv;
    cudaGetSymbolAddress((void**)&h,     g_h);
    cudaGetSymbolAddress((void**)&qkv,   g_qkv);
    cudaGetSymbolAddress((void**)&ctx,   g_ctx);
    cudaGetSymbolAddress((void**)&x1,    g_x1);
    cudaGetSymbolAddress((void**)&h2,    g_h2);
    cudaGetSymbolAddress((void**)&ff,    g_ff);
    cudaGetSymbolAddress((void**)&wqkvT, g_wqkvT);
    cudaGetSymbolAddress((void**)&bqkv,  g_bqkv);
    cudaGetSymbolAddress((void**)&woT,   g_woT);
    cudaGetSymbolAddress((void**)&w1T,   g_w1T);
    cudaGetSymbolAddress((void**)&w2T,   g_w2T);

    cudaFuncSetAttribute(attn_f16_kernel, cudaFuncAttributeMaxDynamicSharedMemorySize, ATTN_SMEM);
    cudaFuncSetAttribute(gemm_f16<0,1>, cudaFuncAttributeMaxDynamicSharedMemorySize, GEMM_SMEM_BYTES);
    cudaFuncSetAttribute(gemm_f16<1,0>, cudaFuncAttributeMaxDynamicSharedMemorySize, GEMM_SMEM_BYTES);
    cudaFuncSetAttribute(gemm_f16<2,1>, cudaFuncAttributeMaxDynamicSharedMemorySize, GEMM_SMEM_BYTES);

    const dim3 gQKV(QLD / BN, TOK / BM);     // (48, 64)
    const dim3 gProj(DM / BN, TOK / BM);     // (16, 64)
    const dim3 gFF1(DFF / BN, TOK / BM);     // (64, 64)

    // launch 0: fused weight prep + LN1 (co-scheduled, one launch)
    prep_ln_kernel<<<PREPLN_BLOCKS, 256>>>(Wq, Wk, Wv, bq, bk, bv, Wo, W1, W2,
                                           wqkvT, bqkv, woT, w1T, w2T,
                                           x, ln1_g, ln1_b, h);
    // launch 1: fused qkv projection (fp16 out)
    gemm_f16<0,1><<<gQKV, 256, GEMM_SMEM_BYTES>>>(h, wqkvT, bqkv, nullptr, qkv, TOK, QLD, DM);
    // launch 2: flash attention (register-resident P)
    attn_f16_kernel<<<dim3(SEQ / 128, NH, BATCH), 256, ATTN_SMEM>>>(qkv, ctx);
    // launch 3 (ncu capture): x1 = x + ctx @ Wo + bo (fp32 out, res prefetched to L2)
    gemm_f16<1,0><<<gProj, 256, GEMM_SMEM_BYTES>>>(ctx, woT, bo, x, x1, TOK, DM, DM);
    // launch 4: LN2 -> fp16
    ln_kernel<<<TOK, 256>>>(x1, ln2_g, ln2_b, h2);
    // launch 5: ff = gelu(h2 @ W1 + b1) (fp16 out)
    gemm_f16<2,1><<<gFF1, 256, GEMM_SMEM_BYTES>>>(h2, w1T, b1, nullptr, ff, TOK, DFF, DM);
    // launch 6: out = x1 + ff @ W2 + b2 (fp32 out, res prefetched to L2)
    gemm_f16<1,0><<<gProj, 256, GEMM_SMEM_BYTES>>>(ff, w2T, b2, x1, out, TOK, DM, DFF);
}

// round 17
// speedup vs baseline: 1.0166x; 1.0166x over previous
#include <cuda_runtime.h>
#include <cuda_fp16.h>
#include <math.h>
#include <stdint.h>

#define TOK   8192
#define DM    1024
#define DFF   4096
#define NH    16
#define DK    64
#define SEQ   2048
#define BATCH 4
#define QLD   (3 * DM)

// ---------------- scratch ----------------
__device__ __half g_h   [TOK * DM];
__device__ __half g_qkv [TOK * QLD];
__device__ __half g_ctx [TOK * DM];
__device__ float  g_x1  [TOK * DM];
__device__ __half g_h2  [TOK * DM];
__device__ __half g_ff  [TOK * DFF];
// fp16 weights, transposed to [N][K]
__device__ __half g_wqkvT[QLD * DM];
__device__ float  g_bqkv [QLD];
__device__ __half g_woT  [DM * DM];
__device__ __half g_w1T  [DFF * DM];
__device__ __half g_w2T  [DM * DFF];

// ---------------- helpers ----------------
__device__ __forceinline__ uint32_t smem_u32(const void* p) {
    uint32_t a;
    asm("{ .reg .u64 t; cvta.to.shared.u64 t, %1; cvt.u32.u64 %0, t; }" : "=r"(a) : "l"(p));
    return a;
}
__device__ __forceinline__ void cp_async16(uint32_t dst, const void* src) {
    asm volatile("cp.async.cg.shared.global [%0], [%1], 16;" :: "r"(dst), "l"(src));
}
__device__ __forceinline__ void cp_commit() {
    asm volatile("cp.async.commit_group;" ::: "memory");
}
__device__ __forceinline__ void mma_f16_16x8x16(float* d, const uint32_t* a, const uint32_t* b) {
    asm volatile(
        "mma.sync.aligned.m16n8k16.row.col.f32.f16.f16.f32 "
        "{%0,%1,%2,%3}, {%4,%5,%6,%7}, {%8,%9}, {%0,%1,%2,%3};"
        : "+f"(d[0]), "+f"(d[1]), "+f"(d[2]), "+f"(d[3])
        : "r"(a[0]), "r"(a[1]), "r"(a[2]), "r"(a[3]), "r"(b[0]), "r"(b[1]));
}
__device__ __forceinline__ void ldmatrix_x4(uint32_t* r, uint32_t addr) {
    asm volatile("ldmatrix.sync.aligned.m8n8.x4.shared.b16 {%0,%1,%2,%3}, [%4];"
        : "=r"(r[0]), "=r"(r[1]), "=r"(r[2]), "=r"(r[3]) : "r"(addr));
}
__device__ __forceinline__ void ldmatrix_x2(uint32_t* r, uint32_t addr) {
    asm volatile("ldmatrix.sync.aligned.m8n8.x2.shared.b16 {%0,%1}, [%2];"
        : "=r"(r[0]), "=r"(r[1]) : "r"(addr));
}
__device__ __forceinline__ void ldmatrix_x4_trans(uint32_t* r, uint32_t addr) {
    asm volatile("ldmatrix.sync.aligned.m8n8.x4.trans.shared.b16 {%0,%1,%2,%3}, [%4];"
        : "=r"(r[0]), "=r"(r[1]), "=r"(r[2]), "=r"(r[3]) : "r"(addr));
}
__device__ __forceinline__ uint32_t pack_h2(float x, float y) {
    __half2 h = __floats2half2_rn(x, y);
    return *(uint32_t*)&h;
}

// ---------------- fused prep + LN1: ONE launch ----------------
#define PREP_BLOCKS 6145
#define PREPLN_BLOCKS (PREP_BLOCKS + TOK)

__global__ void __launch_bounds__(256) prep_ln_kernel(
    const float* __restrict__ Wq, const float* __restrict__ Wk, const float* __restrict__ Wv,
    const float* __restrict__ bq, const float* __restrict__ bk, const float* __restrict__ bv,
    const float* __restrict__ Wo, const float* __restrict__ W1, const float* __restrict__ W2,
    __half* __restrict__ wqkvT, float* __restrict__ bqkv,
    __half* __restrict__ woT, __half* __restrict__ w1T, __half* __restrict__ w2T,
    const float* __restrict__ x, const float* __restrict__ ln1g, const float* __restrict__ ln1b,
    __half* __restrict__ hout)
{
    const int id = blockIdx.x;
    const int t = threadIdx.x;

    if (id >= PREP_BLOCKS) {
        // ---- LN1 row ----
        const int row = id - PREP_BLOCKS;
        const float4 v = ((const float4*)(x + (size_t)row * DM))[t];

        float s  = v.x + v.y + v.z + v.w;
        float ss = v.x * v.x + v.y * v.y + v.z * v.z + v.w * v.w;
        #pragma unroll
        for (int o = 16; o; o >>= 1) {
            s  += __shfl_xor_sync(0xffffffffu, s,  o);
            ss += __shfl_xor_sync(0xffffffffu, ss, o);
        }
        __shared__ float sb[8], sb2[8];
        if ((t & 31) == 0) { sb[t >> 5] = s; sb2[t >> 5] = ss; }
        __syncthreads();
        float ts = 0.f, ts2 = 0.f;
        #pragma unroll
        for (int i = 0; i < 8; i++) { ts += sb[i]; ts2 += sb2[i]; }

        const float mu  = ts * (1.0f / DM);
        const float var = ts2 * (1.0f / DM) - mu * mu;
        const float inv = rsqrtf(var + 1e-5f);

        const float4 gg = ((const float4*)ln1g)[t];
        const float4 bb = ((const float4*)ln1b)[t];
        uint2 o;
        o.x = pack_h2((v.x - mu) * inv * gg.x + bb.x, (v.y - mu) * inv * gg.y + bb.y);
        o.y = pack_h2((v.z - mu) * inv * gg.z + bb.z, (v.w - mu) * inv * gg.w + bb.w);
        ((uint2*)(hout + (size_t)row * DM))[t] = o;
        return;
    }

    if (id == PREP_BLOCKS - 1) {
        #pragma unroll
        for (int j = 0; j < 3; j++) {
            const int idx = j * 256 + t;
            const int which = idx >> 8, c4 = idx & 255;
            const float* src = which == 0 ? bq : (which == 1 ? bk : bv);
            ((float4*)bqkv)[which * 256 + c4] = ((const float4*)src)[c4];
        }
        return;
    }

    const int tx = t & 31, ty = t >> 5;
    const float* in; __half* out; int R, C, lid;
    if (id < 2048) {
        const int m = id >> 9; lid = id & 511;
        in = m == 0 ? Wq : (m == 1 ? Wk : (m == 2 ? Wv : Wo));
        out = (m == 3) ? woT : (wqkvT + (size_t)m * DM * DM);
        R = DM; C = DM;
    } else if (id < 4096) {
        lid = id - 2048; in = W1; out = w1T; R = DM; C = DFF;
    } else {
        lid = id - 4096; in = W2; out = w2T; R = DFF; C = DM;
    }
    const int tilesC = C / 32;
    const int r0 = (lid / tilesC) * 64, c0 = (lid % tilesC) * 32;

    __shared__ float tile[64][33];
    #pragma unroll
    for (int i = ty; i < 64; i += 8)
        tile[i][tx] = in[(size_t)(r0 + i) * C + c0 + tx];
    __syncthreads();

    const int orow = t >> 3, seg = t & 7;
    float f[8];
    #pragma unroll
    for (int j = 0; j < 8; j++) f[j] = tile[seg * 8 + j][orow];
    uint4 u;
    u.x = pack_h2(f[0], f[1]); u.y = pack_h2(f[2], f[3]);
    u.z = pack_h2(f[4], f[5]); u.w = pack_h2(f[6], f[7]);
    *(uint4*)(out + (size_t)(c0 + orow) * R + r0 + seg * 8) = u;
}

// ---------------- LayerNorm (standalone, for LN2) ----------------
__global__ void __launch_bounds__(256) ln_kernel(const float* __restrict__ x,
                                                 const float* __restrict__ g,
                                                 const float* __restrict__ b,
                                                 __half* __restrict__ out)
{
    const int row = blockIdx.x;
    const int tid = threadIdx.x;
    const float4 v = ((const float4*)(x + (size_t)row * DM))[tid];

    float s  = v.x + v.y + v.z + v.w;
    float ss = v.x * v.x + v.y * v.y + v.z * v.z + v.w * v.w;
    #pragma unroll
    for (int o = 16; o; o >>= 1) {
        s  += __shfl_xor_sync(0xffffffffu, s,  o);
        ss += __shfl_xor_sync(0xffffffffu, ss, o);
    }
    __shared__ float sb[8], sb2[8];
    if ((tid & 31) == 0) { sb[tid >> 5] = s; sb2[tid >> 5] = ss; }
    __syncthreads();
    float ts = 0.f, ts2 = 0.f;
    #pragma unroll
    for (int i = 0; i < 8; i++) { ts += sb[i]; ts2 += sb2[i]; }

    const float mu  = ts * (1.0f / DM);
    const float var = ts2 * (1.0f / DM) - mu * mu;
    const float inv = rsqrtf(var + 1e-5f);

    const float4 gg = ((const float4*)g)[tid];
    const float4 bb = ((const float4*)b)[tid];
    uint2 o;
    o.x = pack_h2((v.x - mu) * inv * gg.x + bb.x, (v.y - mu) * inv * gg.y + bb.y);
    o.y = pack_h2((v.z - mu) * inv * gg.z + bb.z, (v.w - mu) * inv * gg.w + bb.w);
    ((uint2*)(out + (size_t)row * DM))[tid] = o;
}

// ---------------- GELU ----------------
__device__ __forceinline__ float gelu_exact(float v) {
    return 0.5f * v * (1.0f + erff(v * 0.70710678118654752440f));
}

#define BKH 64
#define TSH 72                          // halves per smem row = 144 bytes

// ---------------- BIG fp16 GEMM: 128x128 tile, 8 warps 32x32, 3-stage, 2 CTAs/SM ----------------
// (measured fastest for long-K many-wave GEMMs: QKV, FF1)
#define GBM 128
#define GBN 128
#define G_TILE_HALVES (128 * TSH)
#define G_STAGE_BYTES (2 * G_TILE_HALVES * 2)
#define BIG_SMEM_BYTES (3 * G_STAGE_BYTES)

template <int EPI, int OUTH>
__global__ void __launch_bounds__(256, 2) gemm_big(
    const __half* __restrict__ A, const __half* __restrict__ BT,
    const float* __restrict__ bias, const float* __restrict__ res,
    void* __restrict__ Cv, int M, int N, int K)
{
    extern __shared__ __half smh[];
    const uint32_t sbase = smem_u32(smh);

    const int tid = threadIdx.x;
    const int wid = tid >> 5;
    const int lane = tid & 31;
    const int g = lane >> 2;
    const int tig = lane & 3;
    const int wm = wid & 1;
    const int wn = wid >> 1;

    const uint32_t aRow = (uint32_t)((lane & 15) * 144 + (lane >> 4) * 16);
    const uint32_t bRow = (uint32_t)((lane & 7) * 144 + ((lane >> 3) & 1) * 16);

    const int n0 = blockIdx.x * GBN;
    const int m0 = blockIdx.y * GBM;
    const int NT = K / BKH;

    float acc[4][4][4];
    #pragma unroll
    for (int mt = 0; mt < 4; mt++)
        #pragma unroll
        for (int nt = 0; nt < 4; nt++)
            #pragma unroll
            for (int e = 0; e < 4; e++) acc[mt][nt][e] = 0.f;

    auto load_stage = [&](int st, int t) {
        const uint32_t aoff = sbase + (uint32_t)st * G_STAGE_BYTES;
        const uint32_t boff = aoff + G_TILE_HALVES * 2;
        #pragma unroll
        for (int i = 0; i < 4; i++) {
            const int idx = i * 256 + tid;
            const int row = idx >> 3, ch = idx & 7;
            cp_async16(aoff + (uint32_t)(row * TSH + ch * 8) * 2u,
                       A + (size_t)(m0 + row) * K + (size_t)t * BKH + ch * 8);
            cp_async16(boff + (uint32_t)(row * TSH + ch * 8) * 2u,
                       BT + (size_t)(n0 + row) * K + (size_t)t * BKH + ch * 8);
        }
    };

    #pragma unroll
    for (int t = 0; t < 2; t++) {
        load_stage(t, t);
        cp_commit();
    }

    for (int t = 0; t < NT; t++) {
        asm volatile("cp.async.wait_group 1;" ::: "memory");
        __syncthreads();

        const int pf = t + 2;
        if (pf < NT) load_stage(pf % 3, pf);
        cp_commit();

        const int st = t % 3;
        const uint32_t aBase = sbase + (uint32_t)st * G_STAGE_BYTES + (uint32_t)(wm * 64) * 144 + aRow;
        const uint32_t bBase = sbase + (uint32_t)st * G_STAGE_BYTES + G_TILE_HALVES * 2
                             + (uint32_t)(wn * 32) * 144 + bRow;

        #pragma unroll
        for (int ks = 0; ks < 4; ks++) {
            const uint32_t kb = (uint32_t)(ks * 32);
            uint32_t afr[2][4], bfr[4][2];
            #pragma unroll
            for (int mt = 0; mt < 2; mt++)
                ldmatrix_x4(afr[mt], aBase + (uint32_t)(mt * 16) * 144 + kb);
            #pragma unroll
            for (int nt = 0; nt < 4; nt++)
                ldmatrix_x2(bfr[nt], bBase + (uint32_t)(nt * 8) * 144 + kb);
            #pragma unroll
            for (int mt = 0; mt < 2; mt++)
                #pragma unroll
                for (int nt = 0; nt < 4; nt++) {
                    mma_f16_16x8x16(acc[2 * mt][nt],     afr[mt], bfr[nt]);
                }
            // second pair of m-tiles (reuse bfr)
            #pragma unroll
            for (int mt = 0; mt < 2; mt++)
                ldmatrix_x4(afr[mt], aBase + (uint32_t)((mt * 16) + 32) * 144 + kb);
            #pragma unroll
            for (int mt = 0; mt < 2; mt++)
                #pragma unroll
                for (int nt = 0; nt < 4; nt++)
                    mma_f16_16x8x16(acc[2 * mt + 1][nt], afr[mt], bfr[nt]);
        }
    }

    #pragma unroll
    for (int mt = 0; mt < 4; mt++) {
        // acc[2*j+k] holds m-tile rows: j in {0,1} from first/second ld pair interleave
        const int mrow = (mt & 1) * 32 + (mt >> 1) * 16;   // 0,32,16,48
        const int r0 = m0 + wm * 64 + mrow + g;
        const float* rr0 = (EPI == 1) ? (res + (size_t)r0 * N) : nullptr;
        const float* rr1 = (EPI == 1) ? (res + (size_t)(r0 + 8) * N) : nullptr;
        #pragma unroll
        for (int nt = 0; nt < 4; nt++) {
            const int col = n0 + wn * 32 + nt * 8 + 2 * tig;
            const float bx = bias[col], by = bias[col + 1];
            float v0 = acc[mt][nt][0] + bx, v1 = acc[mt][nt][1] + by;
            float v2 = acc[mt][nt][2] + bx, v3 = acc[mt][nt][3] + by;
            if (EPI == 2) {
                v0 = gelu_exact(v0); v1 = gelu_exact(v1);
                v2 = gelu_exact(v2); v3 = gelu_exact(v3);
            }
            if (EPI == 1) {
                v0 += rr0[col]; v1 += rr0[col + 1];
                v2 += rr1[col]; v3 += rr1[col + 1];
            }
            if (OUTH) {
                __half* C = (__half*)Cv;
                *(uint32_t*)(C + (size_t)r0 * N + col)       = pack_h2(v0, v1);
                *(uint32_t*)(C + (size_t)(r0 + 8) * N + col) = pack_h2(v2, v3);
            } else {
                float* C = (float*)Cv;
                *(float2*)(C + (size_t)r0 * N + col)       = make_float2(v0, v1);
                *(float2*)(C + (size_t)(r0 + 8) * N + col) = make_float2(v2, v3);
            }
        }
    }
}

// ---------------- fp16 GEMM: 128x64 tile, warp 32x32, 2-stage, 3 CTAs/SM (Wo, FF2) ----------------
#define BM 128
#define BN 64
#define A_TILE_HALVES (BM * TSH)
#define B_TILE_HALVES (BN * TSH)
#define STAGE_BYTES ((A_TILE_HALVES + B_TILE_HALVES) * 2)
#define GEMM_SMEM_BYTES (2 * STAGE_BYTES)

template <int EPI, int OUTH>
__global__ void __launch_bounds__(256, 3) gemm_f16(
    const __half* __restrict__ A, const __half* __restrict__ BT,
    const float* __restrict__ bias, const float* __restrict__ res,
    void* __restrict__ Cv, int M, int N, int K)
{
    extern __shared__ __half smh[];
    const uint32_t sbase = smem_u32(smh);

    const int tid = threadIdx.x;
    const int wid = tid >> 5;
    const int lane = tid & 31;
    const int g = lane >> 2;
    const int tig = lane & 3;
    const int wm = wid & 3;
    const int wn = wid >> 2;

    const uint32_t aRow  = (uint32_t)((lane & 15) * 144 + (lane >> 4) * 16);
    const uint32_t bRow2 = (uint32_t)((lane & 7) * 144 + ((lane >> 3) & 1) * 16 + (lane >> 4) * (8 * 144));

    const int n0 = blockIdx.x * BN;
    const int m0 = blockIdx.y * BM;
    const int NT = K / BKH;

    float acc[2][4][4];
    #pragma unroll
    for (int mt = 0; mt < 2; mt++)
        #pragma unroll
        for (int nt = 0; nt < 4; nt++)
            #pragma unroll
            for (int e = 0; e < 4; e++) acc[mt][nt][e] = 0.f;

    auto load_stage = [&](int st, int t) {
        const uint32_t aoff = sbase + (uint32_t)st * STAGE_BYTES;
        const uint32_t boff = aoff + A_TILE_HALVES * 2;
        #pragma unroll
        for (int i = 0; i < 6; i++) {
            const int idx = i * 256 + tid;
            if (idx < 1024) {
                const int row = idx >> 3, ch = idx & 7;
                cp_async16(aoff + (uint32_t)(row * TSH + ch * 8) * 2u,
                           A + (size_t)(m0 + row) * K + (size_t)t * BKH + ch * 8);
            } else {
                const int j = idx - 1024;
                const int row = j >> 3, ch = j & 7;
                cp_async16(boff + (uint32_t)(row * TSH + ch * 8) * 2u,
                           BT + (size_t)(n0 + row) * K + (size_t)t * BKH + ch * 8);
            }
        }
    };

    load_stage(0, 0);
    cp_commit();

    for (int t = 0; t < NT; t++) {
        asm volatile("cp.async.wait_group 0;" ::: "memory");
        __syncthreads();

        if (t + 1 < NT) { load_stage((t + 1) & 1, t + 1); cp_commit(); }

        const int st = t & 1;
        const uint32_t aBase = sbase + (uint32_t)st * STAGE_BYTES + (uint32_t)(wm * 32) * 144 + aRow;
        const uint32_t bBase = sbase + (uint32_t)st * STAGE_BYTES + A_TILE_HALVES * 2
                             + (uint32_t)(wn * 32) * 144 + bRow2;

        #pragma unroll
        for (int ks = 0; ks < 4; ks++) {
            const uint32_t kb = (uint32_t)(ks * 32);
            uint32_t afr[2][4], bfr[2][4];
            #pragma unroll
            for (int mt = 0; mt < 2; mt++)
                ldmatrix_x4(afr[mt], aBase + (uint32_t)(mt * 16) * 144 + kb);
            #pragma unroll
            for (int p = 0; p < 2; p++)
                ldmatrix_x4(bfr[p], bBase + (uint32_t)(p * 16) * 144 + kb);
            #pragma unroll
            for (int mt = 0; mt < 2; mt++)
                #pragma unroll
                for (int nt = 0; nt < 4; nt++)
                    mma_f16_16x8x16(acc[mt][nt], afr[mt], &bfr[nt >> 1][(nt & 1) * 2]);
        }
    }

    #pragma unroll
    for (int mt = 0; mt < 2; mt++) {
        const int r0 = m0 + wm * 32 + mt * 16 + g;
        const float* rr0 = (EPI == 1) ? (res + (size_t)r0 * N) : nullptr;
        const float* rr1 = (EPI == 1) ? (res + (size_t)(r0 + 8) * N) : nullptr;
        #pragma unroll
        for (int nt = 0; nt < 4; nt++) {
            const int col = n0 + wn * 32 + nt * 8 + 2 * tig;
            const float bx = bias[col], by = bias[col + 1];
            float v0 = acc[mt][nt][0] + bx, v1 = acc[mt][nt][1] + by;
            float v2 = acc[mt][nt][2] + bx, v3 = acc[mt][nt][3] + by;
            if (EPI == 2) {
                v0 = gelu_exact(v0); v1 = gelu_exact(v1);
                v2 = gelu_exact(v2); v3 = gelu_exact(v3);
            }
            if (EPI == 1) {
                v0 += rr0[col]; v1 += rr0[col + 1];
                v2 += rr1[col]; v3 += rr1[col + 1];
            }
            if (OUTH) {
                __half* C = (__half*)Cv;
                *(uint32_t*)(C + (size_t)r0 * N + col)       = pack_h2(v0, v1);
                *(uint32_t*)(C + (size_t)(r0 + 8) * N + col) = pack_h2(v2, v3);
            } else {
                float* C = (float*)Cv;
                *(float2*)(C + (size_t)r0 * N + col)       = make_float2(v0, v1);
                *(float2*)(C + (size_t)(r0 + 8) * N + col) = make_float2(v2, v3);
            }
        }
    }
}

// ---------------- fp16 flash attention: register-resident P ----------------
#define KV 64
#define KSH 72
#define VSH 72
#define K_TILE_HALVES (KV * KSH)
#define V_TILE_HALVES (KV * VSH)
#define ATTN_SMEM ((2 * K_TILE_HALVES + 2 * V_TILE_HALVES) * 2)

__global__ void __launch_bounds__(256, 2) attn_f16_kernel(const __half* __restrict__ qkv,
                                                          __half* __restrict__ out)
{
    extern __shared__ __half smh[];
    const uint32_t sbase = smem_u32(smh);
    const uint32_t vtsBase = sbase + 2 * K_TILE_HALVES * 2;

    const int tid = threadIdx.x;
    const int w = tid >> 5;
    const int lane = tid & 31;
    const int g = lane >> 2;
    const int tig = lane & 3;

    const uint32_t bRow2 = (uint32_t)((lane & 7) * 144 + ((lane >> 3) & 1) * 16 + (lane >> 4) * (8 * 144));
    const uint32_t vRowT = (uint32_t)(((lane & 7) + ((lane >> 3) & 1) * 8) * 144 + (lane >> 4) * 16);

    const int qt = blockIdx.x, h = blockIdx.y, b = blockIdx.z;

    uint32_t qa[4][4];
    {
        const __half* qb = qkv + ((size_t)(b * SEQ + qt * 128 + w * 16)) * QLD + h * DK;
        const __half2 sc = __floats2half2_rn(0.125f, 0.125f);
        #pragma unroll
        for (int ks = 0; ks < 4; ks++) {
            const int c = ks * 16 + 2 * tig;
            __half2 a0 = __hmul2(*(const __half2*)(qb + (size_t)g * QLD + c), sc);
            __half2 a1 = __hmul2(*(const __half2*)(qb + (size_t)(g + 8) * QLD + c), sc);
            __half2 a2 = __hmul2(*(const __half2*)(qb + (size_t)g * QLD + c + 8), sc);
            __half2 a3 = __hmul2(*(const __half2*)(qb + (size_t)(g + 8) * QLD + c + 8), sc);
            qa[ks][0] = *(uint32_t*)&a0; qa[ks][1] = *(uint32_t*)&a1;
            qa[ks][2] = *(uint32_t*)&a2; qa[ks][3] = *(uint32_t*)&a3;
        }
    }

    float o[8][4];
    #pragma unroll
    for (int nt = 0; nt < 8; nt++)
        #pragma unroll
        for (int e = 0; e < 4; e++) o[nt][e] = 0.f;
    float m0 = -1e30f, m1 = -1e30f, l0 = 0.f, l1 = 0.f;

    auto load_kv = [&](int t, int buf) {
        const uint32_t kdst = sbase + (uint32_t)(buf * K_TILE_HALVES) * 2u;
        const uint32_t vdst = vtsBase + (uint32_t)(buf * V_TILE_HALVES) * 2u;
        const __half* ksrc = qkv + ((size_t)(b * SEQ + t * KV)) * QLD + DM + h * DK;
        const __half* vsrc = qkv + ((size_t)(b * SEQ + t * KV)) * QLD + 2 * DM + h * DK;
        const int kr0 = tid >> 3, kc = tid & 7;
        cp_async16(kdst + (uint32_t)(kr0 * KSH + kc * 8) * 2u,
                   ksrc + (size_t)kr0 * QLD + kc * 8);
        cp_async16(kdst + (uint32_t)((kr0 + 32) * KSH + kc * 8) * 2u,
                   ksrc + (size_t)(kr0 + 32) * QLD + kc * 8);
        cp_async16(vdst + (uint32_t)(kr0 * VSH + kc * 8) * 2u,
                   vsrc + (size_t)kr0 * QLD + kc * 8);
        cp_async16(vdst + (uint32_t)((kr0 + 32) * VSH + kc * 8) * 2u,
                   vsrc + (size_t)(kr0 + 32) * QLD + kc * 8);
    };

    load_kv(0, 0);
    cp_commit();

    const int NKV = SEQ / KV;
    for (int t = 0; t < NKV; t++) {
        asm volatile("cp.async.wait_group 0;" ::: "memory");
        __syncthreads();
        if (t + 1 < NKV) { load_kv(t + 1, (t + 1) & 1); cp_commit(); }

        float s[8][4];
        #pragma unroll
        for (int nt = 0; nt < 8; nt++)
            #pragma unroll
            for (int e = 0; e < 4; e++) s[nt][e] = 0.f;
        {
            const uint32_t kTile = sbase + (uint32_t)((t & 1) * K_TILE_HALVES) * 2u + bRow2;
            #pragma unroll
            for (int ks = 0; ks < 4; ks++) {
                const uint32_t kb = (uint32_t)(ks * 32);
                #pragma unroll
                for (int p = 0; p < 4; p++) {
                    uint32_t bp[4];
                    ldmatrix_x4(bp, kTile + (uint32_t)(p * 16) * 144 + kb);
                    mma_f16_16x8x16(s[2 * p],     qa[ks], bp);
                    mma_f16_16x8x16(s[2 * p + 1], qa[ks], bp + 2);
                }
            }
        }

        float rmax0 = -1e30f, rmax1 = -1e30f;
        #pragma unroll
        for (int nt = 0; nt < 8; nt++) {
            rmax0 = fmaxf(rmax0, fmaxf(s[nt][0], s[nt][1]));
            rmax1 = fmaxf(rmax1, fmaxf(s[nt][2], s[nt][3]));
        }
        rmax0 = fmaxf(rmax0, __shfl_xor_sync(0xffffffffu, rmax0, 1));
        rmax0 = fmaxf(rmax0, __shfl_xor_sync(0xffffffffu, rmax0, 2));
        rmax1 = fmaxf(rmax1, __shfl_xor_sync(0xffffffffu, rmax1, 1));
        rmax1 = fmaxf(rmax1, __shfl_xor_sync(0xffffffffu, rmax1, 2));

        const float mn0 = fmaxf(m0, rmax0);
        const float mn1 = fmaxf(m1, rmax1);
        const float al0 = __expf(m0 - mn0);
        const float al1 = __expf(m1 - mn1);
        m0 = mn0; m1 = mn1;

        uint32_t pa[4][4];
        float rs0 = 0.f, rs1 = 0.f;
        #pragma unroll
        for (int ks = 0; ks < 4; ks++) {
            const float p00 = __expf(s[2 * ks][0] - mn0);
            const float p01 = __expf(s[2 * ks][1] - mn0);
            const float p02 = __expf(s[2 * ks][2] - mn1);
            const float p03 = __expf(s[2 * ks][3] - mn1);
            const float p10 = __expf(s[2 * ks + 1][0] - mn0);
            const float p11 = __expf(s[2 * ks + 1][1] - mn0);
            const float p12 = __expf(s[2 * ks + 1][2] - mn1);
            const float p13 = __expf(s[2 * ks + 1][3] - mn1);
            rs0 += (p00 + p01) + (p10 + p11);
            rs1 += (p02 + p03) + (p12 + p13);
            pa[ks][0] = pack_h2(p00, p01);
            pa[ks][1] = pack_h2(p02, p03);
            pa[ks][2] = pack_h2(p10, p11);
            pa[ks][3] = pack_h2(p12, p13);
        }
        rs0 += __shfl_xor_sync(0xffffffffu, rs0, 1);
        rs0 += __shfl_xor_sync(0xffffffffu, rs0, 2);
        rs1 += __shfl_xor_sync(0xffffffffu, rs1, 1);
        rs1 += __shfl_xor_sync(0xffffffffu, rs1, 2);
        l0 = l0 * al0 + rs0;
        l1 = l1 * al1 + rs1;

        #pragma unroll
        for (int nt = 0; nt < 8; nt++) {
            o[nt][0] *= al0; o[nt][1] *= al0;
            o[nt][2] *= al1; o[nt][3] *= al1;
        }

        {
            const uint32_t vTile = vtsBase + (uint32_t)((t & 1) * V_TILE_HALVES) * 2u + vRowT;
            #pragma unroll
            for (int ks = 0; ks < 4; ks++) {
                const uint32_t vk = vTile + (uint32_t)(ks * 16) * 144;
                #pragma unroll
                for (int p = 0; p < 4; p++) {
                    uint32_t bp[4];
                    ldmatrix_x4_trans(bp, vk + (uint32_t)(p * 32));
                    mma_f16_16x8x16(o[2 * p],     pa[ks], bp);
                    mma_f16_16x8x16(o[2 * p + 1], pa[ks], bp + 2);
                }
            }
        }
    }

    {
        const float i0 = 1.0f / l0, i1 = 1.0f / l1;
        const int r0 = qt * 128 + w * 16 + g;
        __half* ob0 = out + ((size_t)(b * SEQ + r0)) * DM + h * DK + 2 * tig;
        __half* ob1 = ob0 + 8 * DM;
        #pragma unroll
        for (int nt = 0; nt < 8; nt++) {
            *(uint32_t*)(ob0 + nt * 8) = pack_h2(o[nt][0] * i0, o[nt][1] * i0);
            *(uint32_t*)(ob1 + nt * 8) = pack_h2(o[nt][2] * i1, o[nt][3] * i1);
        }
    }
}

// ---------------- host launcher ----------------
extern "C" void kernel_launch(void* const* d_in, const int* in_sizes, int n_in,
                              void* d_out, int out_size)
{
    (void)in_sizes; (void)n_in; (void)out_size;
    const float* x     = (const float*)d_in[0];
    const float* Wq    = (const float*)d_in[1];
    const float* bq    = (const float*)d_in[2];
    const float* Wk    = (const float*)d_in[3];
    const float* bk    = (const float*)d_in[4];
    const float* Wv    = (const float*)d_in[5];
    const float* bv    = (const float*)d_in[6];
    const float* Wo    = (const float*)d_in[7];
    const float* bo    = (const float*)d_in[8];
    const float* ln1_g = (const float*)d_in[9];
    const float* ln1_b = (const float*)d_in[10];
    const float* W1    = (const float*)d_in[11];
    const float* b1    = (const float*)d_in[12];
    const float* W2    = (const float*)d_in[13];
    const float* b2    = (const float*)d_in[14];
    const float* ln2_g = (const float*)d_in[15];
    const float* ln2_b = (const float*)d_in[16];
    float* out = (float*)d_out;

    __half *h, *qkv, *ctx, *h2, *ff, *wqkvT, *woT, *w1T, *w2T;
    float *x1, *bqkv;
    cudaGetSymbolAddress((void**)&h,     g_h);
    cudaGetSymbolAddress((void**)&qkv,   g_qkv);
    cudaGetSymbolAddress((void**)&ctx,   g_ctx);
    cudaGetSymbolAddress((void**)&x1,    g_x1);
    cudaGetSymbolAddress((void**)&h2,    g_h2);
    cudaGetSymbolAddress((void**)&ff,    g_ff);
    cudaGetSymbolAddress((void**)&wqkvT, g_wqkvT);
    cudaGetSymbolAddress((void**)&bqkv,  g_bqkv);
    cudaGetSymbolAddress((void**)&woT,   g_woT);
    cudaGetSymbolAddress((void**)&w1T,   g_w1T);
    cudaGetSymbolAddress((void**)&w2T,   g_w2T);

    cudaFuncSetAttribute(attn_f16_kernel, cudaFuncAttributeMaxDynamicSharedMemorySize, ATTN_SMEM);
    cudaFuncSetAttribute(gemm_big<0,1>, cudaFuncAttributeMaxDynamicSharedMemorySize, BIG_SMEM_BYTES);
    cudaFuncSetAttribute(gemm_big<2,1>, cudaFuncAttributeMaxDynamicSharedMemorySize, BIG_SMEM_BYTES);
    cudaFuncSetAttribute(gemm_f16<1,0>, cudaFuncAttributeMaxDynamicSharedMemorySize, GEMM_SMEM_BYTES);

    const dim3 gQKV(QLD / GBN, TOK / GBM);   // (24, 64)
    const dim3 gProj(DM / BN, TOK / BM);     // (16, 64)
    const dim3 gFF1(DFF / GBN, TOK / GBM);   // (32, 64)

    // launch 0: fused weight prep + LN1
    prep_ln_kernel<<<PREPLN_BLOCKS, 256>>>(Wq, Wk, Wv, bq, bk, bv, Wo, W1, W2,
                                           wqkvT, bqkv, woT, w1T, w2T,
                                           x, ln1_g, ln1_b, h);
    // launch 1: fused qkv projection (big tile, fp16 out)
    gemm_big<0,1><<<gQKV, 256, BIG_SMEM_BYTES>>>(h, wqkvT, bqkv, nullptr, qkv, TOK, QLD, DM);
    // launch 2: flash attention (register-resident P)
    attn_f16_kernel<<<dim3(SEQ / 128, NH, BATCH), 256, ATTN_SMEM>>>(qkv, ctx);
    // launch 3: x1 = x + ctx @ Wo + bo (fp32 out)
    gemm_f16<1,0><<<gProj, 256, GEMM_SMEM_BYTES>>>(ctx, woT, bo, x, x1, TOK, DM, DM);
    // launch 4: LN2 -> fp16
    ln_kernel<<<TOK, 256>>>(x1, ln2_g, ln2_b, h2);
    // launch 5: ff = gelu(h2 @ W1 + b1) (big tile, fp16 out)
    gemm_big<2,1><<<gFF1, 256, BIG_SMEM_BYTES>>>(h2, w1T, b1, nullptr, ff, TOK, DFF, DM);
    // launch 6: out = x1 + ff @ W2 + b2 (fp32 out)
    gemm_f16<1,0><<<gProj, 256, GEMM_SMEM_BYTES>>>(ff, w2T, b2, x1, out, TOK, DM, DFF);
}